// round 14
// baseline (speedup 1.0000x reference)
#include <cuda_runtime.h>
#include <stdint.h>
#include <math.h>

#define B_ 8
#define S_ 2048
#define DSTATE 1024
#define H_ 16
#define DH_ 64
#define PROJW 4096
#define M_ (B_ * S_)   // 16384

typedef unsigned long long u64;

// Scratch (device globals: allocation-free, graph-capturable)
__device__ float g_proj[(size_t)M_ * PROJW];   // 256 MB
__device__ float g_hseq[(size_t)M_ * DSTATE];  // 64 MB
__device__ float g_y[(size_t)M_ * DSTATE];     // 64 MB

__device__ __forceinline__ float* sel_buf(int s, const void* ext) {
    switch (s) {
        case 1: return g_proj;
        case 2: return g_hseq;
        case 3: return g_y;
        default: return (float*)ext;
    }
}

// Packed 2-wide fp32 FMA (Blackwell FFMA2; ptxas never auto-emits it)
#define FMA2(d, a, b) \
    asm("fma.rn.f32x2 %0, %1, %2, %0;" : "+l"(d) : "l"(a), "l"(b))
#define PACK2(d, lo, hi) \
    asm("mov.b64 %0, {%1, %2};" : "=l"(d) : "r"(lo), "r"(hi))

// ---------------------------------------------------------------------------
// GEMM: C[M,N] = A[M,K] @ B[K,N], row-major. 128x128 tile, BK=8, 256 thr,
// 8x8 microtile via f32x2. A tile stored DUPLICATED in smem ((v,v) pairs) so
// the per-k DUP2/MOV stream disappears: per k-step = 8 broadcast LDS.64 (A)
// + 2 contiguous LDS.128 (B) + 32 FFMA2, nothing else.
// ---------------------------------------------------------------------------
__global__ __launch_bounds__(256, 2) void gemm128(const void* Aext, int a_sel,
                                                  const float* __restrict__ Bm,
                                                  void* Cext, int c_sel,
                                                  int M, int N, int K)
{
    const float* __restrict__ A = sel_buf(a_sel, Aext);
    float* __restrict__ C = sel_buf(c_sel, Cext);

    __shared__ float As2[2][8][256];   // duplicated pairs: [k][2r]=[k][2r+1]=A
    __shared__ float Bs[2][8][128];

    const int tid = threadIdx.x;
    const int bm = blockIdx.y * 128;
    const int bn = blockIdx.x * 128;
    const int tx = tid & 15;   // cols: tx*4..+3 and 64+tx*4..+3
    const int ty = tid >> 4;   // rows: ty*8..+7

    u64 acc2[8][4] = {};       // [i][0,1]: cols tx*4+{01,23}; [i][2,3]: +64

    const int am = tid >> 1;
    const int ak = (tid & 1) * 4;
    const int bk  = tid >> 5;
    const int bn4 = (tid & 31) * 4;

    const float* Aptr = A + (size_t)(bm + am) * K + ak;
    const float* Bptr = Bm + (size_t)bk * N + bn + bn4;

    float4 av = *(const float4*)(Aptr);
    float4 bv = *(const float4*)(Bptr);

    int buf = 0;
    for (int k0 = 0; k0 < K; k0 += 8) {
        *(float2*)&As2[buf][ak + 0][2 * am] = make_float2(av.x, av.x);
        *(float2*)&As2[buf][ak + 1][2 * am] = make_float2(av.y, av.y);
        *(float2*)&As2[buf][ak + 2][2 * am] = make_float2(av.z, av.z);
        *(float2*)&As2[buf][ak + 3][2 * am] = make_float2(av.w, av.w);
        *(float4*)&Bs[buf][bk][bn4] = bv;
        __syncthreads();

        if (k0 + 8 < K) {
            av = *(const float4*)(Aptr + k0 + 8);
            bv = *(const float4*)(Bptr + (size_t)(k0 + 8) * N);
        }

#pragma unroll
        for (int k = 0; k < 8; k++) {
            u64 a2[8], b2[4];
#pragma unroll
            for (int i = 0; i < 8; i++)   // broadcast LDS.64 (2 addrs/warp)
                a2[i] = *(const u64*)&As2[buf][k][2 * (ty * 8 + i)];
            ulonglong2 bb0 = *(const ulonglong2*)&Bs[buf][k][tx * 4];       // contiguous
            ulonglong2 bb1 = *(const ulonglong2*)&Bs[buf][k][64 + tx * 4];  // contiguous
            b2[0] = bb0.x; b2[1] = bb0.y; b2[2] = bb1.x; b2[3] = bb1.y;

#pragma unroll
            for (int i = 0; i < 8; i++)
#pragma unroll
                for (int j2 = 0; j2 < 4; j2++)
                    FMA2(acc2[i][j2], a2[i], b2[j2]);
        }
        buf ^= 1;
    }

#pragma unroll
    for (int i = 0; i < 8; i++) {
        float2 p0 = *(float2*)&acc2[i][0];
        float2 p1 = *(float2*)&acc2[i][1];
        float2 p2 = *(float2*)&acc2[i][2];
        float2 p3 = *(float2*)&acc2[i][3];
        float* Crow = C + (size_t)(bm + ty * 8 + i) * N + bn;
        *(float4*)(Crow + tx * 4)      = make_float4(p0.x, p0.y, p1.x, p1.y);
        *(float4*)(Crow + 64 + tx * 4) = make_float4(p2.x, p2.y, p3.x, p3.y);
    }
}

// ---------------------------------------------------------------------------
// Recurrence: one block per (b, h). 64 threads. hs kept DUPLICATED in smem
// ((v,v) pairs) so phase-1 needs no DUP2; h carried in register; 4 FFMA2
// chains per phase.
// ---------------------------------------------------------------------------
__global__ __launch_bounds__(64, 1) void recur_kernel(const float* __restrict__ Wall)
{
    __shared__ float hs2[128];   // duplicated: hs2[2d] = hs2[2d+1] = h[d]
    __shared__ float rh[64];

    const int b = blockIdx.x >> 4;
    const int h = blockIdx.x & 15;
    const int e = threadIdx.x;

    u64 wrf[64];   // (Wr[d][e], Wf[d][e])
    u64 wc2[32];   // (Wc[2j][e], Wc[2j+1][e])
    {
        const float* Wc = Wall + (size_t)h * 4096 + e;
        const float* Wf = Wall + (size_t)(16 + h) * 4096 + e;
        const float* Wr = Wall + (size_t)(32 + h) * 4096 + e;
#pragma unroll
        for (int d = 0; d < 64; d++)
            PACK2(wrf[d], __float_as_uint(Wr[d * 64]), __float_as_uint(Wf[d * 64]));
#pragma unroll
        for (int j = 0; j < 32; j++)
            PACK2(wc2[j], __float_as_uint(Wc[2 * j * 64]), __float_as_uint(Wc[(2 * j + 1) * 64]));
    }

    hs2[2 * e] = 0.f; hs2[2 * e + 1] = 0.f;
    float hprev = 0.f;
    __syncthreads();

    const float* xp = g_proj + (size_t)b * S_ * PROJW + h * DH_ + e;
    float* op = g_hseq + (size_t)b * S_ * DSTATE + h * DH_ + e;

    float xi = xp[0], xf = xp[1024], xr = xp[2048];

    for (int t = 0; t < S_; t++) {
        xp += PROJW;
        float nxi = 0.f, nxf = 0.f, nxr = 0.f;
        if (t + 1 < S_) { nxi = xp[0]; nxf = xp[1024]; nxr = xp[2048]; }

        u64 arf0 = 0, arf1 = 0, arf2 = 0, arf3 = 0;  // 4 chains, lanes (r,f)
#pragma unroll
        for (int d4 = 0; d4 < 64; d4 += 4) {
            ulonglong2 hd01 = *(const ulonglong2*)&hs2[2 * d4];      // (h,h),(h,h)
            ulonglong2 hd23 = *(const ulonglong2*)&hs2[2 * d4 + 4];
            FMA2(arf0, hd01.x, wrf[d4 + 0]);
            FMA2(arf1, hd01.y, wrf[d4 + 1]);
            FMA2(arf2, hd23.x, wrf[d4 + 2]);
            FMA2(arf3, hd23.y, wrf[d4 + 3]);
        }
        float2 s0 = *(float2*)&arf0;
        float2 s1 = *(float2*)&arf1;
        float2 s2 = *(float2*)&arf2;
        float2 s3 = *(float2*)&arf3;
        float r = 1.f / (1.f + __expf(-(xr + (s0.x + s1.x) + (s2.x + s3.x))));
        float f = 1.f / (1.f + __expf(-(xf + (s0.y + s1.y) + (s2.y + s3.y))));
        rh[e] = r * hprev;
        __syncthreads();   // rh visible; all hs2 reads of this step done

        u64 ac0 = 0, ac1 = 0, ac2 = 0, ac3 = 0;
#pragma unroll
        for (int d8 = 0; d8 < 64; d8 += 8) {
            ulonglong2 rv0 = *(const ulonglong2*)&rh[d8];
            ulonglong2 rv1 = *(const ulonglong2*)&rh[d8 + 4];
            FMA2(ac0, rv0.x, wc2[d8 / 2 + 0]);
            FMA2(ac1, rv0.y, wc2[d8 / 2 + 1]);
            FMA2(ac2, rv1.x, wc2[d8 / 2 + 2]);
            FMA2(ac3, rv1.y, wc2[d8 / 2 + 3]);
        }
        float2 c0 = *(float2*)&ac0;
        float2 c1 = *(float2*)&ac1;
        float2 c2 = *(float2*)&ac2;
        float2 c3 = *(float2*)&ac3;
        float c = tanhf(xi + (c0.x + c0.y) + (c1.x + c1.y) + (c2.x + c2.y) + (c3.x + c3.y));
        float hnew = f * hprev + (1.f - f) * c;

        *(float2*)&hs2[2 * e] = make_float2(hnew, hnew);  // safe: reads done pre-bar
        hprev = hnew;
        *op = hnew;
        op += DSTATE;
        xi = nxi; xf = nxf; xr = nxr;
        __syncthreads();   // hs2 update visible before next step
    }
}

// ---------------------------------------------------------------------------
// Gated SiLU + RMSNorm (proven)
// ---------------------------------------------------------------------------
__global__ __launch_bounds__(256) void gate_norm_kernel(const float* __restrict__ nw)
{
    const int row = blockIdx.x;
    const float* g    = g_proj + (size_t)row * PROJW + 3072;
    const float* hrow = g_hseq + (size_t)row * DSTATE;
    float* yrow = g_y + (size_t)row * DSTATE;
    const int tid = threadIdx.x;

    float v[4];
    float ss = 0.f;
#pragma unroll
    for (int i = 0; i < 4; i++) {
        int c = tid + i * 256;
        float gv = g[c];
        float hv = hrow[c];
        float yv = hv * gv / (1.f + __expf(-gv));
        v[i] = yv;
        ss += yv * yv;
    }

    __shared__ float red[8];
#pragma unroll
    for (int o = 16; o; o >>= 1) ss += __shfl_xor_sync(0xffffffffu, ss, o);
    if ((tid & 31) == 0) red[tid >> 5] = ss;
    __syncthreads();
    if (tid < 8) {
        float s = red[tid];
#pragma unroll
        for (int o = 4; o; o >>= 1) s += __shfl_xor_sync(0xffu, s, o);
        if (tid == 0) red[0] = s;
    }
    __syncthreads();
    const float scale = rsqrtf(red[0] * (1.f / 1024.f) + 1e-6f);

#pragma unroll
    for (int i = 0; i < 4; i++) {
        int c = tid + i * 256;
        yrow[c] = v[i] * scale * nw[c];
    }
}

// ---------------------------------------------------------------------------
// Launch — kernel launches ONLY.
// ---------------------------------------------------------------------------
extern "C" void kernel_launch(void* const* d_in, const int* in_sizes, int n_in,
                              void* d_out, int out_size)
{
    const float* x      = (const float*)d_in[0];  // [8,2048,1024]
    const float* w_in   = (const float*)d_in[1];  // [1024,4096]
    const float* s_w    = (const float*)d_in[2];  // [48,64,64]
    const float* norm_w = (const float*)d_in[3];  // [1024]
    const float* w_out  = (const float*)d_in[4];  // [1024,1024]

    // 1) input projection: x[16384,1024] @ w_in[1024,4096] -> g_proj
    {
        dim3 grid(PROJW / 128, M_ / 128);
        gemm128<<<grid, 256>>>(x, 0, w_in, nullptr, 1, M_, PROJW, 1024);
    }

    // 2) recurrence -> g_hseq
    recur_kernel<<<B_ * H_, 64>>>(s_w);

    // 3) gated silu + rmsnorm -> g_y
    gate_norm_kernel<<<M_, 256>>>(norm_w);

    // 4) output projection: g_y[16384,1024] @ w_out[1024,1024] -> d_out
    {
        dim3 grid(1024 / 128, M_ / 128);
        gemm128<<<grid, 256>>>(nullptr, 3, w_out, d_out, 0, M_, 1024, 1024);
    }
}

// round 15
// speedup vs baseline: 1.3124x; 1.3124x over previous
#include <cuda_runtime.h>
#include <stdint.h>
#include <math.h>

#define B_ 8
#define S_ 2048
#define DSTATE 1024
#define H_ 16
#define DH_ 64
#define PROJW 4096
#define M_ (B_ * S_)   // 16384

typedef unsigned long long u64;

// Scratch (device globals: allocation-free, graph-capturable)
__device__ float g_proj[(size_t)M_ * PROJW];   // 256 MB
__device__ float g_hseq[(size_t)M_ * DSTATE];  // 64 MB
__device__ float g_y[(size_t)M_ * DSTATE];     // 64 MB

__device__ __forceinline__ float* sel_buf(int s, const void* ext) {
    switch (s) {
        case 1: return g_proj;
        case 2: return g_hseq;
        case 3: return g_y;
        default: return (float*)ext;
    }
}

// Packed 2-wide fp32 FMA (Blackwell FFMA2; ptxas never auto-emits it)
#define FMA2(d, a, b) \
    asm("fma.rn.f32x2 %0, %1, %2, %0;" : "+l"(d) : "l"(a), "l"(b))
#define DUP2(d, s) \
    asm("mov.b64 %0, {%1, %1};" : "=l"(d) : "r"(s))
#define PACK2(d, lo, hi) \
    asm("mov.b64 %0, {%1, %2};" : "=l"(d) : "r"(lo), "r"(hi))

// ---------------------------------------------------------------------------
// GEMM (exact R13 WIN version): C[M,N] = A[M,K] @ B[K,N]. 128x128 tile,
// BK=8, 256 thr, 8x8 microtile via f32x2, conflict-free split B fragments,
// double-buffered smem, register prefetch, 2 CTAs/SM.
// ---------------------------------------------------------------------------
__global__ __launch_bounds__(256, 2) void gemm128(const void* Aext, int a_sel,
                                                  const float* __restrict__ Bm,
                                                  void* Cext, int c_sel,
                                                  int M, int N, int K)
{
    const float* __restrict__ A = sel_buf(a_sel, Aext);
    float* __restrict__ C = sel_buf(c_sel, Cext);

    __shared__ float As[2][8][128];
    __shared__ float Bs[2][8][128];

    const int tid = threadIdx.x;
    const int bm = blockIdx.y * 128;
    const int bn = blockIdx.x * 128;
    const int tx = tid & 15;   // cols: tx*4..+3 and 64+tx*4..+3
    const int ty = tid >> 4;   // rows: ty*8..+7

    u64 acc2[8][4] = {};

    const int am = tid >> 1;
    const int ak = (tid & 1) * 4;
    const int bk  = tid >> 5;
    const int bn4 = (tid & 31) * 4;

    const float* Aptr = A + (size_t)(bm + am) * K + ak;
    const float* Bptr = Bm + (size_t)bk * N + bn + bn4;

    float4 av = *(const float4*)(Aptr);
    float4 bv = *(const float4*)(Bptr);

    int buf = 0;
    for (int k0 = 0; k0 < K; k0 += 8) {
        As[buf][ak + 0][am] = av.x;
        As[buf][ak + 1][am] = av.y;
        As[buf][ak + 2][am] = av.z;
        As[buf][ak + 3][am] = av.w;
        *(float4*)&Bs[buf][bk][bn4] = bv;
        __syncthreads();

        if (k0 + 8 < K) {
            av = *(const float4*)(Aptr + k0 + 8);
            bv = *(const float4*)(Bptr + (size_t)(k0 + 8) * N);
        }

#pragma unroll
        for (int k = 0; k < 8; k++) {
            uint4 aa0 = *(const uint4*)&As[buf][k][ty * 8];       // broadcast
            uint4 aa1 = *(const uint4*)&As[buf][k][ty * 8 + 4];
            ulonglong2 bb0 = *(const ulonglong2*)&Bs[buf][k][tx * 4];       // contiguous
            ulonglong2 bb1 = *(const ulonglong2*)&Bs[buf][k][64 + tx * 4];  // contiguous

            u64 a2[8], b2[4];
            DUP2(a2[0], aa0.x); DUP2(a2[1], aa0.y);
            DUP2(a2[2], aa0.z); DUP2(a2[3], aa0.w);
            DUP2(a2[4], aa1.x); DUP2(a2[5], aa1.y);
            DUP2(a2[6], aa1.z); DUP2(a2[7], aa1.w);
            b2[0] = bb0.x; b2[1] = bb0.y; b2[2] = bb1.x; b2[3] = bb1.y;

#pragma unroll
            for (int i = 0; i < 8; i++)
#pragma unroll
                for (int j2 = 0; j2 < 4; j2++)
                    FMA2(acc2[i][j2], a2[i], b2[j2]);
        }
        buf ^= 1;
    }

#pragma unroll
    for (int i = 0; i < 8; i++) {
        float2 p0 = *(float2*)&acc2[i][0];
        float2 p1 = *(float2*)&acc2[i][1];
        float2 p2 = *(float2*)&acc2[i][2];
        float2 p3 = *(float2*)&acc2[i][3];
        float* Crow = C + (size_t)(bm + ty * 8 + i) * N + bn;
        *(float4*)(Crow + tx * 4)      = make_float4(p0.x, p0.y, p1.x, p1.y);
        *(float4*)(Crow + 64 + tx * 4) = make_float4(p2.x, p2.y, p3.x, p3.y);
    }
}

// ---------------------------------------------------------------------------
// Recurrence: one block per (b, h), 64 threads, hs duplicated ((v,v) pairs),
// 4 FFMA2 chains per phase. NEW: x prefetch depth 3 — the LDGs for step t+3
// are issued at step t, giving ~2.5 steps (>600 cyc) to cover DRAM latency
// (the 1-step-ahead prefetch left ~150-300 cyc exposed per step).
// ---------------------------------------------------------------------------
__global__ __launch_bounds__(64, 1) void recur_kernel(const float* __restrict__ Wall)
{
    __shared__ float hs2[128];   // duplicated: hs2[2d] = hs2[2d+1] = h[d]
    __shared__ float rh[64];

    const int b = blockIdx.x >> 4;
    const int h = blockIdx.x & 15;
    const int e = threadIdx.x;

    u64 wrf[64];   // (Wr[d][e], Wf[d][e])
    u64 wc2[32];   // (Wc[2j][e], Wc[2j+1][e])
    {
        const float* Wc = Wall + (size_t)h * 4096 + e;
        const float* Wf = Wall + (size_t)(16 + h) * 4096 + e;
        const float* Wr = Wall + (size_t)(32 + h) * 4096 + e;
#pragma unroll
        for (int d = 0; d < 64; d++)
            PACK2(wrf[d], __float_as_uint(Wr[d * 64]), __float_as_uint(Wf[d * 64]));
#pragma unroll
        for (int j = 0; j < 32; j++)
            PACK2(wc2[j], __float_as_uint(Wc[2 * j * 64]), __float_as_uint(Wc[(2 * j + 1) * 64]));
    }

    hs2[2 * e] = 0.f; hs2[2 * e + 1] = 0.f;
    float hprev = 0.f;
    __syncthreads();

    const float* xp = g_proj + (size_t)b * S_ * PROJW + h * DH_ + e;
    float* op = g_hseq + (size_t)b * S_ * DSTATE + h * DH_ + e;

    // prefetch pipeline: cur = x[t], nb0 = x[t+1], nb1 = x[t+2]
    float xi = xp[0],        xf = xp[1024],        xr = xp[2048];
    float i0 = xp[PROJW],     f0 = xp[PROJW + 1024], r0 = xp[PROJW + 2048];
    float i1 = xp[2 * PROJW], f1 = xp[2 * PROJW + 1024], r1 = xp[2 * PROJW + 2048];

    for (int t = 0; t < S_; t++) {
        // issue LDG for x[t+3] immediately (lands ~2.5 steps later)
        float ni = 0.f, nf = 0.f, nr = 0.f;
        if (t + 3 < S_) {
            const float* xq = xp + 3 * PROJW;
            ni = xq[0]; nf = xq[1024]; nr = xq[2048];
        }
        xp += PROJW;

        u64 arf0 = 0, arf1 = 0, arf2 = 0, arf3 = 0;  // 4 chains, lanes (r,f)
#pragma unroll
        for (int d4 = 0; d4 < 64; d4 += 4) {
            ulonglong2 hd01 = *(const ulonglong2*)&hs2[2 * d4];
            ulonglong2 hd23 = *(const ulonglong2*)&hs2[2 * d4 + 4];
            FMA2(arf0, hd01.x, wrf[d4 + 0]);
            FMA2(arf1, hd01.y, wrf[d4 + 1]);
            FMA2(arf2, hd23.x, wrf[d4 + 2]);
            FMA2(arf3, hd23.y, wrf[d4 + 3]);
        }
        float2 s0 = *(float2*)&arf0;
        float2 s1 = *(float2*)&arf1;
        float2 s2 = *(float2*)&arf2;
        float2 s3 = *(float2*)&arf3;
        float r = 1.f / (1.f + __expf(-(xr + (s0.x + s1.x) + (s2.x + s3.x))));
        float f = 1.f / (1.f + __expf(-(xf + (s0.y + s1.y) + (s2.y + s3.y))));
        rh[e] = r * hprev;
        __syncthreads();   // rh visible; all hs2 reads of this step done

        u64 ac0 = 0, ac1 = 0, ac2 = 0, ac3 = 0;
#pragma unroll
        for (int d8 = 0; d8 < 64; d8 += 8) {
            ulonglong2 rv0 = *(const ulonglong2*)&rh[d8];
            ulonglong2 rv1 = *(const ulonglong2*)&rh[d8 + 4];
            FMA2(ac0, rv0.x, wc2[d8 / 2 + 0]);
            FMA2(ac1, rv0.y, wc2[d8 / 2 + 1]);
            FMA2(ac2, rv1.x, wc2[d8 / 2 + 2]);
            FMA2(ac3, rv1.y, wc2[d8 / 2 + 3]);
        }
        float2 c0 = *(float2*)&ac0;
        float2 c1 = *(float2*)&ac1;
        float2 c2 = *(float2*)&ac2;
        float2 c3 = *(float2*)&ac3;
        float c = tanhf(xi + (c0.x + c0.y) + (c1.x + c1.y) + (c2.x + c2.y) + (c3.x + c3.y));
        float hnew = f * hprev + (1.f - f) * c;

        *(float2*)&hs2[2 * e] = make_float2(hnew, hnew);  // safe: reads done pre-bar
        hprev = hnew;
        *op = hnew;
        op += DSTATE;

        // rotate prefetch pipeline
        xi = i0; xf = f0; xr = r0;
        i0 = i1; f0 = f1; r0 = r1;
        i1 = ni; f1 = nf; r1 = nr;
        __syncthreads();   // hs2 update visible before next step
    }
}

// ---------------------------------------------------------------------------
// Gated SiLU + RMSNorm (proven)
// ---------------------------------------------------------------------------
__global__ __launch_bounds__(256) void gate_norm_kernel(const float* __restrict__ nw)
{
    const int row = blockIdx.x;
    const float* g    = g_proj + (size_t)row * PROJW + 3072;
    const float* hrow = g_hseq + (size_t)row * DSTATE;
    float* yrow = g_y + (size_t)row * DSTATE;
    const int tid = threadIdx.x;

    float v[4];
    float ss = 0.f;
#pragma unroll
    for (int i = 0; i < 4; i++) {
        int c = tid + i * 256;
        float gv = g[c];
        float hv = hrow[c];
        float yv = hv * gv / (1.f + __expf(-gv));
        v[i] = yv;
        ss += yv * yv;
    }

    __shared__ float red[8];
#pragma unroll
    for (int o = 16; o; o >>= 1) ss += __shfl_xor_sync(0xffffffffu, ss, o);
    if ((tid & 31) == 0) red[tid >> 5] = ss;
    __syncthreads();
    if (tid < 8) {
        float s = red[tid];
#pragma unroll
        for (int o = 4; o; o >>= 1) s += __shfl_xor_sync(0xffu, s, o);
        if (tid == 0) red[0] = s;
    }
    __syncthreads();
    const float scale = rsqrtf(red[0] * (1.f / 1024.f) + 1e-6f);

#pragma unroll
    for (int i = 0; i < 4; i++) {
        int c = tid + i * 256;
        yrow[c] = v[i] * scale * nw[c];
    }
}

// ---------------------------------------------------------------------------
// Launch — kernel launches ONLY.
// ---------------------------------------------------------------------------
extern "C" void kernel_launch(void* const* d_in, const int* in_sizes, int n_in,
                              void* d_out, int out_size)
{
    const float* x      = (const float*)d_in[0];  // [8,2048,1024]
    const float* w_in   = (const float*)d_in[1];  // [1024,4096]
    const float* s_w    = (const float*)d_in[2];  // [48,64,64]
    const float* norm_w = (const float*)d_in[3];  // [1024]
    const float* w_out  = (const float*)d_in[4];  // [1024,1024]

    // 1) input projection: x[16384,1024] @ w_in[1024,4096] -> g_proj
    {
        dim3 grid(PROJW / 128, M_ / 128);
        gemm128<<<grid, 256>>>(x, 0, w_in, nullptr, 1, M_, PROJW, 1024);
    }

    // 2) recurrence -> g_hseq
    recur_kernel<<<B_ * H_, 64>>>(s_w);

    // 3) gated silu + rmsnorm -> g_y
    gate_norm_kernel<<<M_, 256>>>(norm_w);

    // 4) output projection: g_y[16384,1024] @ w_out[1024,1024] -> d_out
    {
        dim3 grid(1024 / 128, M_ / 128);
        gemm128<<<grid, 256>>>(nullptr, 3, w_out, d_out, 0, M_, 1024, 1024);
    }
}